// round 1
// baseline (speedup 1.0000x reference)
#include <cuda_runtime.h>

#define BB 16
#define TT 2048
#define FF 128
#define UU 256
#define BT (BB*TT)

#define PITCH 260            // 64-row tile pitch in floats (bank-spread, 16B aligned)
#define SCORE_SCALE 0.08838834764831843f   // 1/sqrt(128)

// scratch for sigmoid projections (no cudaMalloc allowed)
__device__ float g_q[(size_t)BT * UU];
__device__ float g_v[(size_t)BT * UU];
__device__ float g_k[(size_t)BT * UU];

__device__ __forceinline__ float dot4(const float4& a, const float4& b) {
    return a.x * b.x + a.y * b.y + a.z * b.z + a.w * b.w;
}
__device__ __forceinline__ void fma4(float4& o, float p, const float4& k) {
    o.x += p * k.x; o.y += p * k.y; o.z += p * k.z; o.w += p * k.w;
}
__device__ __forceinline__ float sigmoidf(float z) {
    return 1.0f / (1.0f + __expf(-z));
}

// ---------------------------------------------------------------------------
// Projection: out = sigmoid(x @ W)   x:[BT,128] W:[128,256]
// tile 128M x 128N, 256 threads, 8x8 register tile, K=128 staged fully.
// ---------------------------------------------------------------------------
__global__ __launch_bounds__(256, 1)
void proj_kernel(const float* __restrict__ x,
                 const float* __restrict__ W0,
                 const float* __restrict__ W1,
                 const float* __restrict__ W2)
{
    const float* W  = (blockIdx.z == 0) ? W0 : (blockIdx.z == 1 ? W1 : W2);
    float*       out = (blockIdx.z == 0) ? g_q : (blockIdx.z == 1 ? g_v : g_k);
    const int m0 = blockIdx.x * 128;
    const int n0 = blockIdx.y * 128;

    extern __shared__ float sm[];
    float* xsT = sm;              // [128 k][132 i]  (transposed x tile)
    float* Ws  = sm + 128 * 132;  // [128 k][128 j]

    const int tid = threadIdx.x;

    // load x tile [128 rows][128 k], store transposed
    #pragma unroll
    for (int it = 0; it < 16; ++it) {
        int idx = tid + it * 256;        // float4 index, 32 per row
        int i   = idx >> 5;
        int k4  = (idx & 31) << 2;
        float4 v = *(const float4*)(x + (size_t)(m0 + i) * FF + k4);
        xsT[(k4 + 0) * 132 + i] = v.x;
        xsT[(k4 + 1) * 132 + i] = v.y;
        xsT[(k4 + 2) * 132 + i] = v.z;
        xsT[(k4 + 3) * 132 + i] = v.w;
    }
    // load W tile [128 k][128 j at n0]
    #pragma unroll
    for (int it = 0; it < 16; ++it) {
        int idx = tid + it * 256;
        int k   = idx >> 5;
        int j4  = (idx & 31) << 2;
        *(float4*)(Ws + k * 128 + j4) = *(const float4*)(W + (size_t)k * UU + n0 + j4);
    }
    __syncthreads();

    const int ty = tid >> 4, tx = tid & 15;
    const int i0 = ty * 8,  j0 = tx * 8;

    float acc[8][8];
    #pragma unroll
    for (int r = 0; r < 8; ++r)
        #pragma unroll
        for (int c = 0; c < 8; ++c) acc[r][c] = 0.f;

    #pragma unroll 4
    for (int k = 0; k < 128; ++k) {
        float4 a0 = *(const float4*)(xsT + k * 132 + i0);
        float4 a1 = *(const float4*)(xsT + k * 132 + i0 + 4);
        float4 b0 = *(const float4*)(Ws  + k * 128 + j0);
        float4 b1 = *(const float4*)(Ws  + k * 128 + j0 + 4);
        float a[8] = {a0.x, a0.y, a0.z, a0.w, a1.x, a1.y, a1.z, a1.w};
        float b[8] = {b0.x, b0.y, b0.z, b0.w, b1.x, b1.y, b1.z, b1.w};
        #pragma unroll
        for (int r = 0; r < 8; ++r)
            #pragma unroll
            for (int c = 0; c < 8; ++c)
                acc[r][c] += a[r] * b[c];
    }

    // sigmoid + store
    #pragma unroll
    for (int r = 0; r < 8; ++r) {
        float* orow = out + (size_t)(m0 + i0 + r) * UU + n0 + j0;
        #pragma unroll
        for (int c4 = 0; c4 < 2; ++c4) {
            float4 v;
            v.x = sigmoidf(acc[r][c4 * 4 + 0]);
            v.y = sigmoidf(acc[r][c4 * 4 + 1]);
            v.z = sigmoidf(acc[r][c4 * 4 + 2]);
            v.w = sigmoidf(acc[r][c4 * 4 + 3]);
            *(float4*)(orow + c4 * 4) = v;
        }
    }
}

// ---------------------------------------------------------------------------
// Flash attention, strict causal (s < t), fp32.
// Block: 64 query rows, loops over 64-row key tiles j=0..m (j=m is diagonal).
// 256 threads as 16x16. S-phase: rows i0=ty*4, cols s=tx+16c.
// O-phase: rows i0=ty*4, cols u=4*tx+64*cc.
// ---------------------------------------------------------------------------
__global__ __launch_bounds__(256, 1)
void attn_kernel(float* __restrict__ out)
{
    const int b  = blockIdx.y;
    const int m  = blockIdx.x;       // 0..31
    const int t0 = m * 64;

    extern __shared__ float sm[];
    float* Qs = sm;                       // [64][PITCH]
    float* Vs = Qs + 64 * PITCH;          // [64][PITCH]  ("v" = keys)
    float* Ks = Vs + 64 * PITCH;          // [64][PITCH]  ("k" = values)
    float* Ps = Ks + 64 * PITCH;          // [64][65]

    const int tid = threadIdx.x;
    const int ty = tid >> 4, tx = tid & 15;
    const int i0 = ty * 4;

    // load Q tile (rows t0..t0+63)
    {
        const float* qg = g_q + ((size_t)b * TT + t0) * UU;
        #pragma unroll
        for (int it = 0; it < 16; ++it) {
            int idx = tid + it * 256;     // 4096 float4, 64 per row
            int r   = idx >> 6;
            int d4  = (idx & 63) << 2;
            *(float4*)(Qs + r * PITCH + d4) = *(const float4*)(qg + r * UU + d4);
        }
    }

    float4 o4[4][4];
    #pragma unroll
    for (int r = 0; r < 4; ++r)
        #pragma unroll
        for (int cc = 0; cc < 4; ++cc) o4[r][cc] = make_float4(0.f, 0.f, 0.f, 0.f);
    float mrow[4], lrow[4];
    #pragma unroll
    for (int r = 0; r < 4; ++r) { mrow[r] = -1e30f; lrow[r] = 0.f; }

    for (int j = 0; j <= m; ++j) {
        const int sbase = j * 64;
        const float* vg = g_v + ((size_t)b * TT + sbase) * UU;
        const float* kg = g_k + ((size_t)b * TT + sbase) * UU;

        __syncthreads();   // prior O-phase reads done before overwriting tiles
        #pragma unroll
        for (int it = 0; it < 16; ++it) {
            int idx = tid + it * 256;
            int r   = idx >> 6;
            int d4  = (idx & 63) << 2;
            *(float4*)(Vs + r * PITCH + d4) = *(const float4*)(vg + r * UU + d4);
            *(float4*)(Ks + r * PITCH + d4) = *(const float4*)(kg + r * UU + d4);
        }
        __syncthreads();

        // ---- S = Q . V^T over d=256 ----
        float acc[4][4];
        #pragma unroll
        for (int r = 0; r < 4; ++r)
            #pragma unroll
            for (int c = 0; c < 4; ++c) acc[r][c] = 0.f;

        #pragma unroll 2
        for (int d = 0; d < UU; d += 4) {
            float4 q0 = *(const float4*)(Qs + (i0 + 0) * PITCH + d);
            float4 q1 = *(const float4*)(Qs + (i0 + 1) * PITCH + d);
            float4 q2 = *(const float4*)(Qs + (i0 + 2) * PITCH + d);
            float4 q3 = *(const float4*)(Qs + (i0 + 3) * PITCH + d);
            float4 v0 = *(const float4*)(Vs + (tx +  0) * PITCH + d);
            float4 v1 = *(const float4*)(Vs + (tx + 16) * PITCH + d);
            float4 v2 = *(const float4*)(Vs + (tx + 32) * PITCH + d);
            float4 v3 = *(const float4*)(Vs + (tx + 48) * PITCH + d);
            acc[0][0] += dot4(q0, v0); acc[0][1] += dot4(q0, v1);
            acc[0][2] += dot4(q0, v2); acc[0][3] += dot4(q0, v3);
            acc[1][0] += dot4(q1, v0); acc[1][1] += dot4(q1, v1);
            acc[1][2] += dot4(q1, v2); acc[1][3] += dot4(q1, v3);
            acc[2][0] += dot4(q2, v0); acc[2][1] += dot4(q2, v1);
            acc[2][2] += dot4(q2, v2); acc[2][3] += dot4(q2, v3);
            acc[3][0] += dot4(q3, v0); acc[3][1] += dot4(q3, v1);
            acc[3][2] += dot4(q3, v2); acc[3][3] += dot4(q3, v3);
        }

        // ---- mask (diagonal tile only) + online softmax ----
        const bool diag = (j == m);
        float psc[4];
        #pragma unroll
        for (int r = 0; r < 4; ++r) {
            float lm = -1e30f;
            #pragma unroll
            for (int c = 0; c < 4; ++c) {
                float sv = acc[r][c] * SCORE_SCALE;
                if (diag && (tx + 16 * c >= i0 + r)) sv = -1e30f;  // strict causal
                acc[r][c] = sv;
                lm = fmaxf(lm, sv);
            }
            lm = fmaxf(lm, __shfl_xor_sync(0xffffffffu, lm, 8, 16));
            lm = fmaxf(lm, __shfl_xor_sync(0xffffffffu, lm, 4, 16));
            lm = fmaxf(lm, __shfl_xor_sync(0xffffffffu, lm, 2, 16));
            lm = fmaxf(lm, __shfl_xor_sync(0xffffffffu, lm, 1, 16));
            const float mn = fmaxf(mrow[r], lm);
            psc[r] = __expf(mrow[r] - mn);
            float rs = 0.f;
            #pragma unroll
            for (int c = 0; c < 4; ++c) {
                float p = __expf(acc[r][c] - mn);
                if (diag && (tx + 16 * c >= i0 + r)) p = 0.f;  // exact zero (also row t=0)
                acc[r][c] = p;
                rs += p;
            }
            rs += __shfl_xor_sync(0xffffffffu, rs, 8, 16);
            rs += __shfl_xor_sync(0xffffffffu, rs, 4, 16);
            rs += __shfl_xor_sync(0xffffffffu, rs, 2, 16);
            rs += __shfl_xor_sync(0xffffffffu, rs, 1, 16);
            lrow[r] = lrow[r] * psc[r] + rs;
            mrow[r] = mn;
        }

        // stage P
        #pragma unroll
        for (int r = 0; r < 4; ++r)
            #pragma unroll
            for (int c = 0; c < 4; ++c)
                Ps[(i0 + r) * 65 + tx + 16 * c] = acc[r][c];
        __syncthreads();

        // rescale running O
        #pragma unroll
        for (int r = 0; r < 4; ++r) {
            const float s = psc[r];
            #pragma unroll
            for (int cc = 0; cc < 4; ++cc) {
                o4[r][cc].x *= s; o4[r][cc].y *= s;
                o4[r][cc].z *= s; o4[r][cc].w *= s;
            }
        }

        // ---- O += P . K ----
        #pragma unroll 2
        for (int s = 0; s < 64; ++s) {
            float p0 = Ps[(i0 + 0) * 65 + s];
            float p1 = Ps[(i0 + 1) * 65 + s];
            float p2 = Ps[(i0 + 2) * 65 + s];
            float p3 = Ps[(i0 + 3) * 65 + s];
            float4 k0 = *(const float4*)(Ks + s * PITCH + 4 * tx +   0);
            float4 k1 = *(const float4*)(Ks + s * PITCH + 4 * tx +  64);
            float4 k2 = *(const float4*)(Ks + s * PITCH + 4 * tx + 128);
            float4 k3 = *(const float4*)(Ks + s * PITCH + 4 * tx + 192);
            fma4(o4[0][0], p0, k0); fma4(o4[0][1], p0, k1);
            fma4(o4[0][2], p0, k2); fma4(o4[0][3], p0, k3);
            fma4(o4[1][0], p1, k0); fma4(o4[1][1], p1, k1);
            fma4(o4[1][2], p1, k2); fma4(o4[1][3], p1, k3);
            fma4(o4[2][0], p2, k0); fma4(o4[2][1], p2, k1);
            fma4(o4[2][2], p2, k2); fma4(o4[2][3], p2, k3);
            fma4(o4[3][0], p3, k0); fma4(o4[3][1], p3, k1);
            fma4(o4[3][2], p3, k2); fma4(o4[3][3], p3, k3);
        }
    }

    // epilogue: normalize; fully-masked row (t=0) -> zeros
    float* og = out + ((size_t)b * TT + t0) * UU;
    #pragma unroll
    for (int r = 0; r < 4; ++r) {
        const float inv = (lrow[r] > 0.f) ? (1.f / lrow[r]) : 0.f;
        #pragma unroll
        for (int cc = 0; cc < 4; ++cc) {
            float4 v = o4[r][cc];
            v.x *= inv; v.y *= inv; v.z *= inv; v.w *= inv;
            *(float4*)(og + (i0 + r) * UU + 4 * tx + 64 * cc) = v;
        }
    }
}

// ---------------------------------------------------------------------------
extern "C" void kernel_launch(void* const* d_in, const int* in_sizes, int n_in,
                              void* d_out, int out_size)
{
    const float* x  = (const float*)d_in[0];
    const float* Wq = (const float*)d_in[1];
    const float* Wv = (const float*)d_in[2];
    const float* Wk = (const float*)d_in[3];
    float* out = (float*)d_out;

    const int proj_smem = (128 * 132 + 128 * 128) * 4;            // 133120
    const int attn_smem = (3 * 64 * PITCH + 64 * 65) * 4;         // 216320

    cudaFuncSetAttribute(proj_kernel, cudaFuncAttributeMaxDynamicSharedMemorySize, proj_smem);
    cudaFuncSetAttribute(attn_kernel, cudaFuncAttributeMaxDynamicSharedMemorySize, attn_smem);

    proj_kernel<<<dim3(BT / 128, UU / 128, 3), 256, proj_smem>>>(x, Wq, Wv, Wk);
    attn_kernel<<<dim3(TT / 64, BB), 256, attn_smem>>>(out);
}

// round 2
// speedup vs baseline: 1.0001x; 1.0001x over previous
#include <cuda_runtime.h>

#define BB 16
#define TT 2048
#define FF 128
#define UU 256
#define BT (BB*TT)

#define PITCH 260            // 64-row tile pitch in floats (bank-spread, 16B aligned)
#define SCORE_SCALE 0.08838834764831843f   // 1/sqrt(128)

// scratch for sigmoid projections (no cudaMalloc allowed)
__device__ float g_q[(size_t)BT * UU];
__device__ float g_v[(size_t)BT * UU];
__device__ float g_k[(size_t)BT * UU];

__device__ __forceinline__ float dot4(const float4& a, const float4& b) {
    return a.x * b.x + a.y * b.y + a.z * b.z + a.w * b.w;
}
__device__ __forceinline__ void fma4(float4& o, float p, const float4& k) {
    o.x += p * k.x; o.y += p * k.y; o.z += p * k.z; o.w += p * k.w;
}
__device__ __forceinline__ float sigmoidf(float z) {
    return 1.0f / (1.0f + __expf(-z));
}

// ---------------------------------------------------------------------------
// Projection: out = sigmoid(x @ W)   x:[BT,128] W:[128,256]
// tile 128M x 128N, 256 threads, 8x8 register tile, K=128 staged fully.
// ---------------------------------------------------------------------------
__global__ __launch_bounds__(256, 1)
void proj_kernel(const float* __restrict__ x,
                 const float* __restrict__ W0,
                 const float* __restrict__ W1,
                 const float* __restrict__ W2)
{
    const float* W  = (blockIdx.z == 0) ? W0 : (blockIdx.z == 1 ? W1 : W2);
    float*       out = (blockIdx.z == 0) ? g_q : (blockIdx.z == 1 ? g_v : g_k);
    const int m0 = blockIdx.x * 128;
    const int n0 = blockIdx.y * 128;

    extern __shared__ float sm[];
    float* xsT = sm;              // [128 k][132 i]  (transposed x tile)
    float* Ws  = sm + 128 * 132;  // [128 k][128 j]

    const int tid = threadIdx.x;

    // load x tile [128 rows][128 k], store transposed
    #pragma unroll
    for (int it = 0; it < 16; ++it) {
        int idx = tid + it * 256;        // float4 index, 32 per row
        int i   = idx >> 5;
        int k4  = (idx & 31) << 2;
        float4 v = *(const float4*)(x + (size_t)(m0 + i) * FF + k4);
        xsT[(k4 + 0) * 132 + i] = v.x;
        xsT[(k4 + 1) * 132 + i] = v.y;
        xsT[(k4 + 2) * 132 + i] = v.z;
        xsT[(k4 + 3) * 132 + i] = v.w;
    }
    // load W tile [128 k][128 j at n0]
    #pragma unroll
    for (int it = 0; it < 16; ++it) {
        int idx = tid + it * 256;
        int k   = idx >> 5;
        int j4  = (idx & 31) << 2;
        *(float4*)(Ws + k * 128 + j4) = *(const float4*)(W + (size_t)k * UU + n0 + j4);
    }
    __syncthreads();

    const int ty = tid >> 4, tx = tid & 15;
    const int i0 = ty * 8,  j0 = tx * 8;

    float acc[8][8];
    #pragma unroll
    for (int r = 0; r < 8; ++r)
        #pragma unroll
        for (int c = 0; c < 8; ++c) acc[r][c] = 0.f;

    #pragma unroll 4
    for (int k = 0; k < 128; ++k) {
        float4 a0 = *(const float4*)(xsT + k * 132 + i0);
        float4 a1 = *(const float4*)(xsT + k * 132 + i0 + 4);
        float4 b0 = *(const float4*)(Ws  + k * 128 + j0);
        float4 b1 = *(const float4*)(Ws  + k * 128 + j0 + 4);
        float a[8] = {a0.x, a0.y, a0.z, a0.w, a1.x, a1.y, a1.z, a1.w};
        float b[8] = {b0.x, b0.y, b0.z, b0.w, b1.x, b1.y, b1.z, b1.w};
        #pragma unroll
        for (int r = 0; r < 8; ++r)
            #pragma unroll
            for (int c = 0; c < 8; ++c)
                acc[r][c] += a[r] * b[c];
    }

    // sigmoid + store
    #pragma unroll
    for (int r = 0; r < 8; ++r) {
        float* orow = out + (size_t)(m0 + i0 + r) * UU + n0 + j0;
        #pragma unroll
        for (int c4 = 0; c4 < 2; ++c4) {
            float4 v;
            v.x = sigmoidf(acc[r][c4 * 4 + 0]);
            v.y = sigmoidf(acc[r][c4 * 4 + 1]);
            v.z = sigmoidf(acc[r][c4 * 4 + 2]);
            v.w = sigmoidf(acc[r][c4 * 4 + 3]);
            *(float4*)(orow + c4 * 4) = v;
        }
    }
}

// ---------------------------------------------------------------------------
// Flash attention, strict causal (s < t), fp32.
// Block: 64 query rows, loops over 64-row key tiles j=0..m (j=m is diagonal).
// 256 threads as 16x16. S-phase: rows i0=ty*4, cols s=tx+16c.
// O-phase: rows i0=ty*4, cols u=4*tx+64*cc.
// ---------------------------------------------------------------------------
__global__ __launch_bounds__(256, 1)
void attn_kernel(float* __restrict__ out)
{
    const int b  = blockIdx.y;
    const int m  = blockIdx.x;       // 0..31
    const int t0 = m * 64;

    extern __shared__ float sm[];
    float* Qs = sm;                       // [64][PITCH]
    float* Vs = Qs + 64 * PITCH;          // [64][PITCH]  ("v" = keys)
    float* Ks = Vs + 64 * PITCH;          // [64][PITCH]  ("k" = values)
    float* Ps = Ks + 64 * PITCH;          // [64][65]

    const int tid = threadIdx.x;
    const int ty = tid >> 4, tx = tid & 15;
    const int i0 = ty * 4;

    // load Q tile (rows t0..t0+63)
    {
        const float* qg = g_q + ((size_t)b * TT + t0) * UU;
        #pragma unroll
        for (int it = 0; it < 16; ++it) {
            int idx = tid + it * 256;     // 4096 float4, 64 per row
            int r   = idx >> 6;
            int d4  = (idx & 63) << 2;
            *(float4*)(Qs + r * PITCH + d4) = *(const float4*)(qg + r * UU + d4);
        }
    }

    float4 o4[4][4];
    #pragma unroll
    for (int r = 0; r < 4; ++r)
        #pragma unroll
        for (int cc = 0; cc < 4; ++cc) o4[r][cc] = make_float4(0.f, 0.f, 0.f, 0.f);
    float mrow[4], lrow[4];
    #pragma unroll
    for (int r = 0; r < 4; ++r) { mrow[r] = -1e30f; lrow[r] = 0.f; }

    for (int j = 0; j <= m; ++j) {
        const int sbase = j * 64;
        const float* vg = g_v + ((size_t)b * TT + sbase) * UU;
        const float* kg = g_k + ((size_t)b * TT + sbase) * UU;

        __syncthreads();   // prior O-phase reads done before overwriting tiles
        #pragma unroll
        for (int it = 0; it < 16; ++it) {
            int idx = tid + it * 256;
            int r   = idx >> 6;
            int d4  = (idx & 63) << 2;
            *(float4*)(Vs + r * PITCH + d4) = *(const float4*)(vg + r * UU + d4);
            *(float4*)(Ks + r * PITCH + d4) = *(const float4*)(kg + r * UU + d4);
        }
        __syncthreads();

        // ---- S = Q . V^T over d=256 ----
        float acc[4][4];
        #pragma unroll
        for (int r = 0; r < 4; ++r)
            #pragma unroll
            for (int c = 0; c < 4; ++c) acc[r][c] = 0.f;

        #pragma unroll 2
        for (int d = 0; d < UU; d += 4) {
            float4 q0 = *(const float4*)(Qs + (i0 + 0) * PITCH + d);
            float4 q1 = *(const float4*)(Qs + (i0 + 1) * PITCH + d);
            float4 q2 = *(const float4*)(Qs + (i0 + 2) * PITCH + d);
            float4 q3 = *(const float4*)(Qs + (i0 + 3) * PITCH + d);
            float4 v0 = *(const float4*)(Vs + (tx +  0) * PITCH + d);
            float4 v1 = *(const float4*)(Vs + (tx + 16) * PITCH + d);
            float4 v2 = *(const float4*)(Vs + (tx + 32) * PITCH + d);
            float4 v3 = *(const float4*)(Vs + (tx + 48) * PITCH + d);
            acc[0][0] += dot4(q0, v0); acc[0][1] += dot4(q0, v1);
            acc[0][2] += dot4(q0, v2); acc[0][3] += dot4(q0, v3);
            acc[1][0] += dot4(q1, v0); acc[1][1] += dot4(q1, v1);
            acc[1][2] += dot4(q1, v2); acc[1][3] += dot4(q1, v3);
            acc[2][0] += dot4(q2, v0); acc[2][1] += dot4(q2, v1);
            acc[2][2] += dot4(q2, v2); acc[2][3] += dot4(q2, v3);
            acc[3][0] += dot4(q3, v0); acc[3][1] += dot4(q3, v1);
            acc[3][2] += dot4(q3, v2); acc[3][3] += dot4(q3, v3);
        }

        // ---- mask (diagonal tile only) + online softmax ----
        const bool diag = (j == m);
        float psc[4];
        #pragma unroll
        for (int r = 0; r < 4; ++r) {
            float lm = -1e30f;
            #pragma unroll
            for (int c = 0; c < 4; ++c) {
                float sv = acc[r][c] * SCORE_SCALE;
                if (diag && (tx + 16 * c >= i0 + r)) sv = -1e30f;  // strict causal
                acc[r][c] = sv;
                lm = fmaxf(lm, sv);
            }
            lm = fmaxf(lm, __shfl_xor_sync(0xffffffffu, lm, 8, 16));
            lm = fmaxf(lm, __shfl_xor_sync(0xffffffffu, lm, 4, 16));
            lm = fmaxf(lm, __shfl_xor_sync(0xffffffffu, lm, 2, 16));
            lm = fmaxf(lm, __shfl_xor_sync(0xffffffffu, lm, 1, 16));
            const float mn = fmaxf(mrow[r], lm);
            psc[r] = __expf(mrow[r] - mn);
            float rs = 0.f;
            #pragma unroll
            for (int c = 0; c < 4; ++c) {
                float p = __expf(acc[r][c] - mn);
                if (diag && (tx + 16 * c >= i0 + r)) p = 0.f;  // exact zero (also row t=0)
                acc[r][c] = p;
                rs += p;
            }
            rs += __shfl_xor_sync(0xffffffffu, rs, 8, 16);
            rs += __shfl_xor_sync(0xffffffffu, rs, 4, 16);
            rs += __shfl_xor_sync(0xffffffffu, rs, 2, 16);
            rs += __shfl_xor_sync(0xffffffffu, rs, 1, 16);
            lrow[r] = lrow[r] * psc[r] + rs;
            mrow[r] = mn;
        }

        // stage P
        #pragma unroll
        for (int r = 0; r < 4; ++r)
            #pragma unroll
            for (int c = 0; c < 4; ++c)
                Ps[(i0 + r) * 65 + tx + 16 * c] = acc[r][c];
        __syncthreads();

        // rescale running O
        #pragma unroll
        for (int r = 0; r < 4; ++r) {
            const float s = psc[r];
            #pragma unroll
            for (int cc = 0; cc < 4; ++cc) {
                o4[r][cc].x *= s; o4[r][cc].y *= s;
                o4[r][cc].z *= s; o4[r][cc].w *= s;
            }
        }

        // ---- O += P . K ----
        #pragma unroll 2
        for (int s = 0; s < 64; ++s) {
            float p0 = Ps[(i0 + 0) * 65 + s];
            float p1 = Ps[(i0 + 1) * 65 + s];
            float p2 = Ps[(i0 + 2) * 65 + s];
            float p3 = Ps[(i0 + 3) * 65 + s];
            float4 k0 = *(const float4*)(Ks + s * PITCH + 4 * tx +   0);
            float4 k1 = *(const float4*)(Ks + s * PITCH + 4 * tx +  64);
            float4 k2 = *(const float4*)(Ks + s * PITCH + 4 * tx + 128);
            float4 k3 = *(const float4*)(Ks + s * PITCH + 4 * tx + 192);
            fma4(o4[0][0], p0, k0); fma4(o4[0][1], p0, k1);
            fma4(o4[0][2], p0, k2); fma4(o4[0][3], p0, k3);
            fma4(o4[1][0], p1, k0); fma4(o4[1][1], p1, k1);
            fma4(o4[1][2], p1, k2); fma4(o4[1][3], p1, k3);
            fma4(o4[2][0], p2, k0); fma4(o4[2][1], p2, k1);
            fma4(o4[2][2], p2, k2); fma4(o4[2][3], p2, k3);
            fma4(o4[3][0], p3, k0); fma4(o4[3][1], p3, k1);
            fma4(o4[3][2], p3, k2); fma4(o4[3][3], p3, k3);
        }
    }

    // epilogue: normalize; fully-masked row (t=0) -> zeros
    float* og = out + ((size_t)b * TT + t0) * UU;
    #pragma unroll
    for (int r = 0; r < 4; ++r) {
        const float inv = (lrow[r] > 0.f) ? (1.f / lrow[r]) : 0.f;
        #pragma unroll
        for (int cc = 0; cc < 4; ++cc) {
            float4 v = o4[r][cc];
            v.x *= inv; v.y *= inv; v.z *= inv; v.w *= inv;
            *(float4*)(og + (i0 + r) * UU + 4 * tx + 64 * cc) = v;
        }
    }
}

// ---------------------------------------------------------------------------
extern "C" void kernel_launch(void* const* d_in, const int* in_sizes, int n_in,
                              void* d_out, int out_size)
{
    const float* x  = (const float*)d_in[0];
    const float* Wq = (const float*)d_in[1];
    const float* Wv = (const float*)d_in[2];
    const float* Wk = (const float*)d_in[3];
    float* out = (float*)d_out;

    const int proj_smem = (128 * 132 + 128 * 128) * 4;            // 133120
    const int attn_smem = (3 * 64 * PITCH + 64 * 65) * 4;         // 216320

    cudaFuncSetAttribute(proj_kernel, cudaFuncAttributeMaxDynamicSharedMemorySize, proj_smem);
    cudaFuncSetAttribute(attn_kernel, cudaFuncAttributeMaxDynamicSharedMemorySize, attn_smem);

    proj_kernel<<<dim3(BT / 128, UU / 128, 3), 256, proj_smem>>>(x, Wq, Wv, Wk);
    attn_kernel<<<dim3(TT / 64, BB), 256, attn_smem>>>(out);
}

// round 5
// speedup vs baseline: 6.1690x; 6.1687x over previous
#include <cuda_runtime.h>
#include <cuda_bf16.h>
#include <cstdint>

#define BB 16
#define TT 2048
#define FF 128
#define UU 256
#define BT (BB*TT)

// sigmoid projections, all row-major bf16 [B*T][U]
__device__ __nv_bfloat16 g_q[(size_t)BT * UU];
__device__ __nv_bfloat16 g_v[(size_t)BT * UU];   // "keys"  (score = q.v)
__device__ __nv_bfloat16 g_k[(size_t)BT * UU];   // "values"

// ---------------------------------------------------------------------------
__device__ __forceinline__ uint32_t smem_u32(const void* p) {
    uint32_t a;
    asm("{ .reg .u64 t; cvta.to.shared.u64 t, %1; cvt.u32.u64 %0, t; }" : "=r"(a) : "l"(p));
    return a;
}
__device__ __forceinline__ void cp16(uint32_t s, const void* g) {
    asm volatile("cp.async.cg.shared.global [%0], [%1], 16;" :: "r"(s), "l"(g));
}
#define CP_COMMIT() asm volatile("cp.async.commit_group;" ::: "memory")
template<int N> __device__ __forceinline__ void cp_wait() {
    asm volatile("cp.async.wait_group %0;" :: "n"(N) : "memory");
}
__device__ __forceinline__ void ldm_x4(uint32_t& r0, uint32_t& r1, uint32_t& r2, uint32_t& r3, uint32_t a) {
    asm volatile("ldmatrix.sync.aligned.m8n8.x4.shared.b16 {%0,%1,%2,%3}, [%4];"
                 : "=r"(r0), "=r"(r1), "=r"(r2), "=r"(r3) : "r"(a));
}
__device__ __forceinline__ void ldm_x4t(uint32_t& r0, uint32_t& r1, uint32_t& r2, uint32_t& r3, uint32_t a) {
    asm volatile("ldmatrix.sync.aligned.m8n8.x4.trans.shared.b16 {%0,%1,%2,%3}, [%4];"
                 : "=r"(r0), "=r"(r1), "=r"(r2), "=r"(r3) : "r"(a));
}
__device__ __forceinline__ void mma16816(float c[4], uint32_t a0, uint32_t a1, uint32_t a2, uint32_t a3,
                                         uint32_t b0, uint32_t b1) {
    asm volatile("mma.sync.aligned.m16n8k16.row.col.f32.bf16.bf16.f32 "
                 "{%0,%1,%2,%3},{%4,%5,%6,%7},{%8,%9},{%0,%1,%2,%3};"
                 : "+f"(c[0]), "+f"(c[1]), "+f"(c[2]), "+f"(c[3])
                 : "r"(a0), "r"(a1), "r"(a2), "r"(a3), "r"(b0), "r"(b1));
}
__device__ __forceinline__ float ex2(float x) {
    float y; asm("ex2.approx.ftz.f32 %0, %1;" : "=f"(y) : "f"(x)); return y;
}
__device__ __forceinline__ float frcp(float x) {
    float y; asm("rcp.approx.ftz.f32 %0, %1;" : "=f"(y) : "f"(x)); return y;
}
__device__ __forceinline__ uint32_t packbf(float a, float b) {
    __nv_bfloat162 v = __floats2bfloat162_rn(a, b);
    return *(uint32_t*)&v;
}

// ---------------------------------------------------------------------------
// Projection: sigmoid(x @ W).  CTA = 128 tokens, 8 warps (16 rows each).
// x smem pitch 272B (136 bf16), W smem pitch 528B (264 bf16) — both 16B-odd
// multiples => ldmatrix conflict-free.
// ---------------------------------------------------------------------------
#define PXO 0
#define PWO (128 * 272)                      // 34816
#define PROJ_SMEM (34816 + 128 * 528)        // 102400

__global__ __launch_bounds__(256, 1)
void proj_kernel(const float* __restrict__ x,
                 const float* __restrict__ W0,
                 const float* __restrict__ W1,
                 const float* __restrict__ W2)
{
    extern __shared__ char sm[];
    const uint32_t smb = smem_u32(sm);
    const int tid = threadIdx.x;
    const int which = blockIdx.y;
    const int m0 = blockIdx.x * 128;
    const float* W = (which == 0) ? W0 : (which == 1 ? W1 : W2);

    // x tile [128 rows][128 d] fp32 -> bf16
    #pragma unroll
    for (int it = 0; it < 16; ++it) {
        int idx = tid + it * 256;
        int r = idx >> 5, c4 = idx & 31;
        float4 v = *(const float4*)(x + (size_t)(m0 + r) * FF + c4 * 4);
        uint2 p; p.x = packbf(v.x, v.y); p.y = packbf(v.z, v.w);
        *(uint2*)(sm + PXO + r * 272 + c4 * 8) = p;
    }
    // W tile [128 k][256 n] fp32 -> bf16
    #pragma unroll
    for (int it = 0; it < 32; ++it) {
        int idx = tid + it * 256;
        int r = idx >> 6, c4 = idx & 63;
        float4 v = *(const float4*)(W + (size_t)r * UU + c4 * 4);
        uint2 p; p.x = packbf(v.x, v.y); p.y = packbf(v.z, v.w);
        *(uint2*)(sm + PWO + r * 528 + c4 * 8) = p;
    }
    __syncthreads();

    const int lane = tid & 31, w = tid >> 5;
    const int lr = lane & 15, lh = lane >> 4;

    float O[32][4];
    #pragma unroll
    for (int i = 0; i < 32; ++i)
        #pragma unroll
        for (int c = 0; c < 4; ++c) O[i][c] = 0.f;

    const uint32_t xa = smb + PXO + (16 * w + lr) * 272 + lh * 16;
    const uint32_t wa = smb + PWO + lr * 528 + lh * 16;

    #pragma unroll
    for (int ks = 0; ks < 8; ++ks) {
        uint32_t a0, a1, a2, a3;
        ldm_x4(a0, a1, a2, a3, xa + ks * 32);
        const uint32_t wrow = wa + ks * 16 * 528;
        #pragma unroll
        for (int i = 0; i < 16; ++i) {
            uint32_t r0, r1, r2, r3;
            ldm_x4t(r0, r1, r2, r3, wrow + i * 32);
            mma16816(O[2 * i],     a0, a1, a2, a3, r0, r1);
            mma16816(O[2 * i + 1], a0, a1, a2, a3, r2, r3);
        }
    }

    // sigmoid + bf16 store
    const float NL2E = -1.4426950408889634f;
    __nv_bfloat16* dst = (which == 0) ? g_q : (which == 1 ? g_v : g_k);
    const int trow0 = m0 + 16 * w + (lane >> 2);
    const int trow1 = trow0 + 8;
    #pragma unroll
    for (int nt = 0; nt < 32; ++nt) {
        int col = 8 * nt + 2 * (lane & 3);
        float s0 = frcp(1.0f + ex2(O[nt][0] * NL2E));
        float s1 = frcp(1.0f + ex2(O[nt][1] * NL2E));
        float s2 = frcp(1.0f + ex2(O[nt][2] * NL2E));
        float s3 = frcp(1.0f + ex2(O[nt][3] * NL2E));
        *(uint32_t*)(dst + (size_t)trow0 * UU + col) = packbf(s0, s1);
        *(uint32_t*)(dst + (size_t)trow1 * UU + col) = packbf(s2, s3);
    }
}

// ---------------------------------------------------------------------------
// Flash attention, strict causal, fixed-max softmax (no online rescale).
// CTA: 128 q-rows, 8 warps x 16 rows; key tiles of 64, K/V double-buffered.
// ---------------------------------------------------------------------------
#define AQ      0
#define AK(s)   (128 * 528 + (s) * 64 * 528)
#define AV(s)   (128 * 528 + 2 * 64 * 528 + (s) * 64 * 528)
#define ATTN_SMEM (384 * 528)    // 202752

__global__ __launch_bounds__(256, 1)
void attn_kernel(float* __restrict__ out)
{
    extern __shared__ char sm[];
    const uint32_t smb = smem_u32(sm);
    const int tid = threadIdx.x;
    const int b = blockIdx.y;
    const int m = (int)gridDim.x - 1 - (int)blockIdx.x;   // heavy CTAs first
    const int t0 = m * 128;
    const int nt = 2 * m + 2;

    const char* qg = (const char*)g_q + (size_t)b * TT * 512;
    const char* kg = (const char*)g_v + (size_t)b * TT * 512;   // keys
    const char* vg = (const char*)g_k + (size_t)b * TT * 512;   // values

    // prologue: Q + K0/V0 (one async group)
    #pragma unroll
    for (int it = 0; it < 16; ++it) {
        int idx = tid + it * 256;
        int r = idx >> 5, c = idx & 31;
        cp16(smb + AQ + r * 528 + c * 16, qg + (size_t)(t0 + r) * 512 + c * 16);
    }
    #pragma unroll
    for (int it = 0; it < 8; ++it) {
        int idx = tid + it * 256;
        int r = idx >> 5, c = idx & 31;
        cp16(smb + AK(0) + r * 528 + c * 16, kg + (size_t)r * 512 + c * 16);
    }
    #pragma unroll
    for (int it = 0; it < 8; ++it) {
        int idx = tid + it * 256;
        int r = idx >> 5, c = idx & 31;
        cp16(smb + AV(0) + r * 528 + c * 16, vg + (size_t)r * 512 + c * 16);
    }
    CP_COMMIT();

    const int lane = tid & 31, w = tid >> 5;
    const int lr = lane & 15, lh = lane >> 4;
    const int trow0 = t0 + 16 * w + (lane >> 2);

    float O[32][4];
    #pragma unroll
    for (int i = 0; i < 32; ++i)
        #pragma unroll
        for (int c = 0; c < 4; ++c) O[i][c] = 0.f;
    float l0 = 0.f, l1 = 0.f;

    const float K1c = 0.08838834764831843f * 1.4426950408889634f;  // scale*log2e
    const float K2c = 23.0f * 1.4426950408889634f;                 // 23*log2e

    for (int j = 0; j < nt; ++j) {
        __syncthreads();   // all warps done with iteration j-1 -> buffers free
        if (j + 1 < nt) {
            const int sb = (j + 1) * 64, nb = (j + 1) & 1;
            #pragma unroll
            for (int it = 0; it < 8; ++it) {
                int idx = tid + it * 256;
                int r = idx >> 5, c = idx & 31;
                cp16(smb + AK(nb) + r * 528 + c * 16, kg + (size_t)(sb + r) * 512 + c * 16);
            }
            #pragma unroll
            for (int it = 0; it < 8; ++it) {
                int idx = tid + it * 256;
                int r = idx >> 5, c = idx & 31;
                cp16(smb + AV(nb) + r * 528 + c * 16, vg + (size_t)(sb + r) * 512 + c * 16);
            }
            CP_COMMIT();
            cp_wait<1>();
        } else {
            cp_wait<0>();
        }
        __syncthreads();   // tile j visible to all warps

        const int buf = j & 1;
        const int sbase = j * 64;

        // ---- S = Q . K^T  (m16 x n64 x k256 per warp) ----
        float S[8][4];
        #pragma unroll
        for (int i = 0; i < 8; ++i)
            #pragma unroll
            for (int c = 0; c < 4; ++c) S[i][c] = 0.f;

        const uint32_t qa = smb + AQ + (16 * w + lr) * 528 + lh * 16;
        const uint32_t ka = smb + AK(buf) + lr * 528 + lh * 16;
        #pragma unroll 4
        for (int ks = 0; ks < 16; ++ks) {
            uint32_t a0, a1, a2, a3;
            ldm_x4(a0, a1, a2, a3, qa + ks * 32);
            #pragma unroll
            for (int g = 0; g < 4; ++g) {
                uint32_t r0, r1, r2, r3;
                ldm_x4(r0, r1, r2, r3, ka + g * 16 * 528 + ks * 32);
                mma16816(S[2 * g],     a0, a1, a2, a3, r0, r2);
                mma16816(S[2 * g + 1], a0, a1, a2, a3, r1, r3);
            }
        }

        // ---- fixed-max softmax + pack P as A-fragments ----
        const bool msk = (sbase >= t0);
        uint32_t P[8][2];
        #pragma unroll
        for (int jt = 0; jt < 8; ++jt) {
            int c0 = sbase + 8 * jt + 2 * (lane & 3);
            float p0 = ex2(fmaf(S[jt][0], K1c, -K2c));
            float p1 = ex2(fmaf(S[jt][1], K1c, -K2c));
            float p2 = ex2(fmaf(S[jt][2], K1c, -K2c));
            float p3 = ex2(fmaf(S[jt][3], K1c, -K2c));
            if (msk) {
                if (c0     >= trow0)     p0 = 0.f;
                if (c0 + 1 >= trow0)     p1 = 0.f;
                if (c0     >= trow0 + 8) p2 = 0.f;
                if (c0 + 1 >= trow0 + 8) p3 = 0.f;
            }
            l0 += p0 + p1;
            l1 += p2 + p3;
            P[jt][0] = packbf(p0, p1);
            P[jt][1] = packbf(p2, p3);
        }

        // ---- O += P . V  (m16 x n256 x k64 per warp) ----
        const uint32_t va = smb + AV(buf) + lr * 528 + lh * 16;
        #pragma unroll
        for (int kt = 0; kt < 4; ++kt) {
            uint32_t a0 = P[2 * kt][0], a1 = P[2 * kt][1];
            uint32_t a2 = P[2 * kt + 1][0], a3 = P[2 * kt + 1][1];
            const uint32_t vrow = va + kt * 16 * 528;
            #pragma unroll
            for (int i = 0; i < 16; ++i) {
                uint32_t r0, r1, r2, r3;
                ldm_x4t(r0, r1, r2, r3, vrow + i * 32);
                mma16816(O[2 * i],     a0, a1, a2, a3, r0, r1);
                mma16816(O[2 * i + 1], a0, a1, a2, a3, r2, r3);
            }
        }
    }

    // ---- epilogue: reduce l across the quad, normalize, store ----
    l0 += __shfl_xor_sync(0xffffffffu, l0, 1);
    l0 += __shfl_xor_sync(0xffffffffu, l0, 2);
    l1 += __shfl_xor_sync(0xffffffffu, l1, 1);
    l1 += __shfl_xor_sync(0xffffffffu, l1, 2);
    const float inv0 = (l0 > 0.f) ? (1.0f / l0) : 0.f;   // row t=0 -> zeros
    const float inv1 = (l1 > 0.f) ? (1.0f / l1) : 0.f;

    float* op0 = out + ((size_t)b * TT + trow0) * UU;
    float* op1 = op0 + 8 * UU;
    #pragma unroll
    for (int ntile = 0; ntile < 32; ++ntile) {
        int col = 8 * ntile + 2 * (lane & 3);
        float2 v0 = make_float2(O[ntile][0] * inv0, O[ntile][1] * inv0);
        float2 v1 = make_float2(O[ntile][2] * inv1, O[ntile][3] * inv1);
        *(float2*)(op0 + col) = v0;
        *(float2*)(op1 + col) = v1;
    }
}

// ---------------------------------------------------------------------------
extern "C" void kernel_launch(void* const* d_in, const int* in_sizes, int n_in,
                              void* d_out, int out_size)
{
    const float* x  = (const float*)d_in[0];
    const float* Wq = (const float*)d_in[1];
    const float* Wv = (const float*)d_in[2];
    const float* Wk = (const float*)d_in[3];
    float* out = (float*)d_out;

    cudaFuncSetAttribute(proj_kernel, cudaFuncAttributeMaxDynamicSharedMemorySize, PROJ_SMEM);
    cudaFuncSetAttribute(attn_kernel, cudaFuncAttributeMaxDynamicSharedMemorySize, ATTN_SMEM);

    proj_kernel<<<dim3(BT / 128, 3), 256, PROJ_SMEM>>>(x, Wq, Wv, Wk);
    attn_kernel<<<dim3(TT / 128, BB), 256, ATTN_SMEM>>>(out);
}

// round 6
// speedup vs baseline: 8.1188x; 1.3161x over previous
#include <cuda_runtime.h>
#include <cuda_bf16.h>
#include <cstdint>

#define BB 16
#define TT 2048
#define FF 128
#define UU 256
#define BT (BB*TT)

// sigmoid projections, all row-major bf16 [B*T][U]
__device__ __nv_bfloat16 g_q[(size_t)BT * UU];
__device__ __nv_bfloat16 g_v[(size_t)BT * UU];   // "keys"  (score = q.v)
__device__ __nv_bfloat16 g_k[(size_t)BT * UU];   // "values"

// ---------------------------------------------------------------------------
__device__ __forceinline__ uint32_t smem_u32(const void* p) {
    uint32_t a;
    asm("{ .reg .u64 t; cvta.to.shared.u64 t, %1; cvt.u32.u64 %0, t; }" : "=r"(a) : "l"(p));
    return a;
}
__device__ __forceinline__ void cp16(uint32_t s, const void* g) {
    asm volatile("cp.async.cg.shared.global [%0], [%1], 16;" :: "r"(s), "l"(g));
}
#define CP_COMMIT() asm volatile("cp.async.commit_group;" ::: "memory")
template<int N> __device__ __forceinline__ void cp_wait() {
    asm volatile("cp.async.wait_group %0;" :: "n"(N) : "memory");
}
__device__ __forceinline__ void ldm_x4(uint32_t& r0, uint32_t& r1, uint32_t& r2, uint32_t& r3, uint32_t a) {
    asm volatile("ldmatrix.sync.aligned.m8n8.x4.shared.b16 {%0,%1,%2,%3}, [%4];"
                 : "=r"(r0), "=r"(r1), "=r"(r2), "=r"(r3) : "r"(a));
}
__device__ __forceinline__ void ldm_x4t(uint32_t& r0, uint32_t& r1, uint32_t& r2, uint32_t& r3, uint32_t a) {
    asm volatile("ldmatrix.sync.aligned.m8n8.x4.trans.shared.b16 {%0,%1,%2,%3}, [%4];"
                 : "=r"(r0), "=r"(r1), "=r"(r2), "=r"(r3) : "r"(a));
}
__device__ __forceinline__ void mma16816(float c[4], uint32_t a0, uint32_t a1, uint32_t a2, uint32_t a3,
                                         uint32_t b0, uint32_t b1) {
    asm volatile("mma.sync.aligned.m16n8k16.row.col.f32.bf16.bf16.f32 "
                 "{%0,%1,%2,%3},{%4,%5,%6,%7},{%8,%9},{%0,%1,%2,%3};"
                 : "+f"(c[0]), "+f"(c[1]), "+f"(c[2]), "+f"(c[3])
                 : "r"(a0), "r"(a1), "r"(a2), "r"(a3), "r"(b0), "r"(b1));
}
__device__ __forceinline__ float ex2(float x) {
    float y; asm("ex2.approx.ftz.f32 %0, %1;" : "=f"(y) : "f"(x)); return y;
}
__device__ __forceinline__ float frcp(float x) {
    float y; asm("rcp.approx.ftz.f32 %0, %1;" : "=f"(y) : "f"(x)); return y;
}
__device__ __forceinline__ uint32_t packbf(float a, float b) {
    __nv_bfloat162 v = __floats2bfloat162_rn(a, b);
    return *(uint32_t*)&v;
}

// ---------------------------------------------------------------------------
// Projection: sigmoid(x @ W).  CTA = 128 tokens, 8 warps (16 rows each).
// ---------------------------------------------------------------------------
#define PXO 0
#define PWO (128 * 272)                      // 34816
#define PROJ_SMEM (34816 + 128 * 528)        // 102400

__global__ __launch_bounds__(256, 1)
void proj_kernel(const float* __restrict__ x,
                 const float* __restrict__ W0,
                 const float* __restrict__ W1,
                 const float* __restrict__ W2)
{
    extern __shared__ char sm[];
    const uint32_t smb = smem_u32(sm);
    const int tid = threadIdx.x;
    const int which = blockIdx.y;
    const int m0 = blockIdx.x * 128;
    const float* W = (which == 0) ? W0 : (which == 1 ? W1 : W2);

    #pragma unroll
    for (int it = 0; it < 16; ++it) {
        int idx = tid + it * 256;
        int r = idx >> 5, c4 = idx & 31;
        float4 v = *(const float4*)(x + (size_t)(m0 + r) * FF + c4 * 4);
        uint2 p; p.x = packbf(v.x, v.y); p.y = packbf(v.z, v.w);
        *(uint2*)(sm + PXO + r * 272 + c4 * 8) = p;
    }
    #pragma unroll
    for (int it = 0; it < 32; ++it) {
        int idx = tid + it * 256;
        int r = idx >> 6, c4 = idx & 63;
        float4 v = *(const float4*)(W + (size_t)r * UU + c4 * 4);
        uint2 p; p.x = packbf(v.x, v.y); p.y = packbf(v.z, v.w);
        *(uint2*)(sm + PWO + r * 528 + c4 * 8) = p;
    }
    __syncthreads();

    const int lane = tid & 31, w = tid >> 5;
    const int lr = lane & 15, lh = lane >> 4;

    float O[32][4];
    #pragma unroll
    for (int i = 0; i < 32; ++i)
        #pragma unroll
        for (int c = 0; c < 4; ++c) O[i][c] = 0.f;

    const uint32_t xa = smb + PXO + (16 * w + lr) * 272 + lh * 16;
    const uint32_t wa = smb + PWO + lr * 528 + lh * 16;

    #pragma unroll
    for (int ks = 0; ks < 8; ++ks) {
        uint32_t a0, a1, a2, a3;
        ldm_x4(a0, a1, a2, a3, xa + ks * 32);
        const uint32_t wrow = wa + ks * 16 * 528;
        #pragma unroll
        for (int i = 0; i < 16; ++i) {
            uint32_t r0, r1, r2, r3;
            ldm_x4t(r0, r1, r2, r3, wrow + i * 32);
            mma16816(O[2 * i],     a0, a1, a2, a3, r0, r1);
            mma16816(O[2 * i + 1], a0, a1, a2, a3, r2, r3);
        }
    }

    const float NL2E = -1.4426950408889634f;
    __nv_bfloat16* dst = (which == 0) ? g_q : (which == 1 ? g_v : g_k);
    const int trow0 = m0 + 16 * w + (lane >> 2);
    const int trow1 = trow0 + 8;
    #pragma unroll
    for (int nt = 0; nt < 32; ++nt) {
        int col = 8 * nt + 2 * (lane & 3);
        float s0 = frcp(1.0f + ex2(O[nt][0] * NL2E));
        float s1 = frcp(1.0f + ex2(O[nt][1] * NL2E));
        float s2 = frcp(1.0f + ex2(O[nt][2] * NL2E));
        float s3 = frcp(1.0f + ex2(O[nt][3] * NL2E));
        *(uint32_t*)(dst + (size_t)trow0 * UU + col) = packbf(s0, s1);
        *(uint32_t*)(dst + (size_t)trow1 * UU + col) = packbf(s2, s3);
    }
}

// ---------------------------------------------------------------------------
// Flash attention, strict causal, fixed-max softmax.
// CTA: 64 q-rows, 4 warps, 128 threads -> 2 CTAs/SM. Key tiles of 32, dbl-buf.
// ---------------------------------------------------------------------------
#define AQ      0
#define AK(s)   (64 * 528 + (s) * 32 * 528)
#define AV(s)   (64 * 528 + 2 * 32 * 528 + (s) * 32 * 528)
#define ATTN_SMEM (192 * 528)    // 101376

__global__ __launch_bounds__(128, 2)
void attn_kernel(float* __restrict__ out)
{
    extern __shared__ char sm[];
    const uint32_t smb = smem_u32(sm);
    const int tid = threadIdx.x;
    const int b = blockIdx.x;
    const int mq = 31 - (int)blockIdx.y;        // heavy CTAs launch first
    const int t0 = mq * 64;
    const int nt = 2 * mq + 2;                  // 32-key tiles

    const char* qg = (const char*)g_q + (size_t)b * TT * 512;
    const char* kg = (const char*)g_v + (size_t)b * TT * 512;   // keys
    const char* vg = (const char*)g_k + (size_t)b * TT * 512;   // values

    // prologue: Q (64 rows) + K0/V0 in one async group
    #pragma unroll
    for (int it = 0; it < 16; ++it) {
        int idx = tid + it * 128;
        int r = idx >> 5, c = idx & 31;
        cp16(smb + AQ + r * 528 + c * 16, qg + (size_t)(t0 + r) * 512 + c * 16);
    }
    #pragma unroll
    for (int it = 0; it < 8; ++it) {
        int idx = tid + it * 128;
        int r = idx >> 5, c = idx & 31;
        cp16(smb + AK(0) + r * 528 + c * 16, kg + (size_t)r * 512 + c * 16);
    }
    #pragma unroll
    for (int it = 0; it < 8; ++it) {
        int idx = tid + it * 128;
        int r = idx >> 5, c = idx & 31;
        cp16(smb + AV(0) + r * 528 + c * 16, vg + (size_t)r * 512 + c * 16);
    }
    CP_COMMIT();

    const int lane = tid & 31, w = tid >> 5;
    const int lr = lane & 15, lh = lane >> 4;
    const int trow0 = t0 + 16 * w + (lane >> 2);
    const int wskip = t0 + 16 * w + 15;   // tile fully masked if sbase >= wskip

    float O[32][4];
    #pragma unroll
    for (int i = 0; i < 32; ++i)
        #pragma unroll
        for (int c = 0; c < 4; ++c) O[i][c] = 0.f;
    float l0 = 0.f, l1 = 0.f;

    const float K1c = 0.08838834764831843f * 1.4426950408889634f;  // scale*log2e
    const float K2c = 23.0f * 1.4426950408889634f;                 // 23*log2e

    for (int j = 0; j < nt; ++j) {
        __syncthreads();
        if (j + 1 < nt) {
            const int sb = (j + 1) * 32, nb = (j + 1) & 1;
            #pragma unroll
            for (int it = 0; it < 8; ++it) {
                int idx = tid + it * 128;
                int r = idx >> 5, c = idx & 31;
                cp16(smb + AK(nb) + r * 528 + c * 16, kg + (size_t)(sb + r) * 512 + c * 16);
            }
            #pragma unroll
            for (int it = 0; it < 8; ++it) {
                int idx = tid + it * 128;
                int r = idx >> 5, c = idx & 31;
                cp16(smb + AV(nb) + r * 528 + c * 16, vg + (size_t)(sb + r) * 512 + c * 16);
            }
            CP_COMMIT();
            cp_wait<1>();
        } else {
            cp_wait<0>();
        }
        __syncthreads();

        const int buf = j & 1;
        const int sbase = j * 32;
        if (sbase >= wskip) continue;       // this warp's rows all masked here

        // ---- S = Q . K^T  (m16 x n32 x k256 per warp) ----
        float S[4][4];
        #pragma unroll
        for (int i = 0; i < 4; ++i)
            #pragma unroll
            for (int c = 0; c < 4; ++c) S[i][c] = 0.f;

        const uint32_t qa = smb + AQ + (16 * w + lr) * 528 + lh * 16;
        const uint32_t ka = smb + AK(buf) + lr * 528 + lh * 16;
        #pragma unroll 4
        for (int ks = 0; ks < 16; ++ks) {
            uint32_t a0, a1, a2, a3;
            ldm_x4(a0, a1, a2, a3, qa + ks * 32);
            #pragma unroll
            for (int g = 0; g < 2; ++g) {
                uint32_t r0, r1, r2, r3;
                ldm_x4(r0, r1, r2, r3, ka + g * 16 * 528 + ks * 32);
                mma16816(S[2 * g],     a0, a1, a2, a3, r0, r2);
                mma16816(S[2 * g + 1], a0, a1, a2, a3, r1, r3);
            }
        }

        // ---- fixed-max softmax + pack P as A-fragments ----
        const bool msk = (sbase + 31 >= trow0);
        uint32_t P[4][2];
        #pragma unroll
        for (int jt = 0; jt < 4; ++jt) {
            int c0 = sbase + 8 * jt + 2 * (lane & 3);
            float p0 = ex2(fmaf(S[jt][0], K1c, -K2c));
            float p1 = ex2(fmaf(S[jt][1], K1c, -K2c));
            float p2 = ex2(fmaf(S[jt][2], K1c, -K2c));
            float p3 = ex2(fmaf(S[jt][3], K1c, -K2c));
            if (msk) {
                if (c0     >= trow0)     p0 = 0.f;
                if (c0 + 1 >= trow0)     p1 = 0.f;
                if (c0     >= trow0 + 8) p2 = 0.f;
                if (c0 + 1 >= trow0 + 8) p3 = 0.f;
            }
            l0 += p0 + p1;
            l1 += p2 + p3;
            P[jt][0] = packbf(p0, p1);
            P[jt][1] = packbf(p2, p3);
        }

        // ---- O += P . V  (m16 x n256 x k32 per warp) ----
        const uint32_t va = smb + AV(buf) + lr * 528 + lh * 16;
        #pragma unroll
        for (int kt = 0; kt < 2; ++kt) {
            uint32_t a0 = P[2 * kt][0], a1 = P[2 * kt][1];
            uint32_t a2 = P[2 * kt + 1][0], a3 = P[2 * kt + 1][1];
            const uint32_t vrow = va + kt * 16 * 528;
            #pragma unroll
            for (int i = 0; i < 16; ++i) {
                uint32_t r0, r1, r2, r3;
                ldm_x4t(r0, r1, r2, r3, vrow + i * 32);
                mma16816(O[2 * i],     a0, a1, a2, a3, r0, r1);
                mma16816(O[2 * i + 1], a0, a1, a2, a3, r2, r3);
            }
        }
    }

    // ---- epilogue: reduce l across the quad, normalize, store ----
    l0 += __shfl_xor_sync(0xffffffffu, l0, 1);
    l0 += __shfl_xor_sync(0xffffffffu, l0, 2);
    l1 += __shfl_xor_sync(0xffffffffu, l1, 1);
    l1 += __shfl_xor_sync(0xffffffffu, l1, 2);
    const float inv0 = (l0 > 0.f) ? (1.0f / l0) : 0.f;   // row t=0 -> zeros
    const float inv1 = (l1 > 0.f) ? (1.0f / l1) : 0.f;

    float* op0 = out + ((size_t)b * TT + trow0) * UU;
    float* op1 = op0 + 8 * UU;
    #pragma unroll
    for (int ntile = 0; ntile < 32; ++ntile) {
        int col = 8 * ntile + 2 * (lane & 3);
        float2 v0 = make_float2(O[ntile][0] * inv0, O[ntile][1] * inv0);
        float2 v1 = make_float2(O[ntile][2] * inv1, O[ntile][3] * inv1);
        *(float2*)(op0 + col) = v0;
        *(float2*)(op1 + col) = v1;
    }
}

// ---------------------------------------------------------------------------
extern "C" void kernel_launch(void* const* d_in, const int* in_sizes, int n_in,
                              void* d_out, int out_size)
{
    const float* x  = (const float*)d_in[0];
    const float* Wq = (const float*)d_in[1];
    const float* Wv = (const float*)d_in[2];
    const float* Wk = (const float*)d_in[3];
    float* out = (float*)d_out;

    cudaFuncSetAttribute(proj_kernel, cudaFuncAttributeMaxDynamicSharedMemorySize, PROJ_SMEM);
    cudaFuncSetAttribute(attn_kernel, cudaFuncAttributeMaxDynamicSharedMemorySize, ATTN_SMEM);

    proj_kernel<<<dim3(BT / 128, 3), 256, PROJ_SMEM>>>(x, Wq, Wv, Wk);
    attn_kernel<<<dim3(BB, TT / 64), 128, ATTN_SMEM>>>(out);
}